// round 15
// baseline (speedup 1.0000x reference)
#include <cuda_runtime.h>
#include <cuda_bf16.h>
#include <cuda_fp16.h>
#include <cstdint>
#include <cstring>

// Problem constants (B=4, Q=256, K=1024, H=128)
#define BB 4
#define QQ 256
#define HH 128
#define KK 1024
#define QT 8             // queries per score block (one per warp)
#define KS 16            // k-splits per query row (score)
#define KCH (KK / KS)    // 64 k-rows per score block (= 2 tiles)
#define T2 32            // k-rows per stage tile
#define PITCHB 272       // bytes per smem tile row (256 data + 16 pad)
#define TILEB (T2 * PITCHB)  // 8704 bytes per buffer
#define CKS 16           // ctx k-splits
#define CKCH (KK / CKS)  // 64 k per ctx block
#define CQT 32           // ctx queries per block
#define CT 32            // ctx k-rows per stage tile

// Scratch (device globals — no allocation allowed)
__device__ __half g_qp[BB * QQ * HH];          // 256 KB
__device__ __half g_kp[BB * KK * HH];          // 1 MB
__device__ __half g_vh[HH];                    // f16 copy of v
__device__ float  g_cpart[CKS * BB * QQ * HH]; // 8 MB ctx partials

__device__ __forceinline__ uint32_t h2u(__half2 h) { uint32_t u; memcpy(&u, &h, 4); return u; }
__device__ __forceinline__ __half2 u2h(uint32_t u) { __half2 h; memcpy(&h, &u, 4); return h; }

__device__ __forceinline__ uint32_t htanh2(uint32_t a) {
    uint32_t r;
    asm("tanh.approx.f16x2 %0, %1;" : "=r"(r) : "r"(a));
    return r;
}

__device__ __forceinline__ void cp_async16(void* dst, const void* src) {
    uint32_t d = (uint32_t)__cvta_generic_to_shared(dst);
    asm volatile("cp.async.ca.shared.global [%0], [%1], 16;\n" :: "r"(d), "l"(src));
}

// ---------------- Projection GEMM: out[row][h] = sum_d in[row][d] * W[h][d]
// Block 0 also publishes the f16 copy of v (g_vh).
__global__ __launch_bounds__(256, 2) void proj_kernel(
    const float* __restrict__ query, const float* __restrict__ key,
    const float* __restrict__ Wq, const float* __restrict__ Wk,
    const float* __restrict__ vvec) {
    extern __shared__ float psm[];
    float4* s_a = (float4*)psm;                   // [32][32] float4, pitch 32
    float4* s_b = (float4*)(psm + 32 * 128);      // [64][33] float4, pitch 33

    if (blockIdx.x == 0 && threadIdx.x < HH)
        g_vh[threadIdx.x] = __float2half(vvec[threadIdx.x]);

    int bx = blockIdx.x;
    const float* in; const float* W; __half* out;
    int rowTile, hTile;
    if (bx < 64) { in = query; W = Wq; out = g_qp; rowTile = (bx >> 1) * 32; hTile = (bx & 1) * 64; }
    else { bx -= 64; in = key; W = Wk; out = g_kp; rowTile = (bx >> 1) * 32; hTile = (bx & 1) * 64; }

    const int tid = threadIdx.x;
    const int tx = tid & 15;
    const int ty = tid >> 4;

    {
        const float4* in4 = (const float4*)(in + (size_t)rowTile * HH);
        const float4* w4 = (const float4*)(W + (size_t)hTile * HH);
        int idx = tid;
#pragma unroll
        for (int i = 0; i < 4; ++i, idx += 256) {
            int r = idx >> 5, c = idx & 31;
            s_a[r * 32 + c] = in4[r * 32 + c];
        }
        idx = tid;
#pragma unroll
        for (int i = 0; i < 8; ++i, idx += 256) {
            int r = idx >> 5, c = idx & 31;
            s_b[r * 33 + c] = w4[r * 32 + c];
        }
    }
    __syncthreads();

    float acc[2][4] = {};
#pragma unroll
    for (int s = 0; s < 32; ++s) {
        float4 a[2], b[4];
#pragma unroll
        for (int i = 0; i < 2; ++i) a[i] = s_a[(ty + 16 * i) * 32 + s];
#pragma unroll
        for (int j = 0; j < 4; ++j) b[j] = s_b[(tx + 16 * j) * 33 + s];
#pragma unroll
        for (int i = 0; i < 2; ++i)
#pragma unroll
            for (int j = 0; j < 4; ++j)
                acc[i][j] += a[i].x * b[j].x + a[i].y * b[j].y
                           + a[i].z * b[j].z + a[i].w * b[j].w;
    }

#pragma unroll
    for (int i = 0; i < 2; ++i)
#pragma unroll
        for (int j = 0; j < 4; ++j)
            out[(size_t)(rowTile + ty + 16 * i) * HH + hTile + tx + 16 * j] =
                __float2half(acc[i][j]);
}

// ---------------- Score kernel: HMMA over tanh(qp+kp) features.
// grid 2048: bx = ((b*32)+qt)*16+ks. 8 warps = 8 queries; each warp covers
// ALL 64 k-rows (2 tiles x 2 row-halves). Single barrier.
__global__ __launch_bounds__(256, 4) void score_kernel(const int* __restrict__ mask,
                                                       float* __restrict__ out_aw) {
    __shared__ __align__(16) unsigned char s_kp[2][TILEB];
    __shared__ __align__(16) __half s_q[QT][HH];   // 2 KB

    const int tid = threadIdx.x;
    const int bx = blockIdx.x;
    const int b = bx >> 9;
    const int qt = (bx >> 4) & 31;
    const int ks = bx & 15;
    const int q0 = qt * QT;
    const int kbase = ks * KCH;
    const int lane = tid & 31;
    const int q = tid >> 5;           // warp == query
    const int t4 = lane & 3;
    const int grp = lane >> 2;

    // ---- stage BOTH kp tiles + 8 q rows up-front (single commit)
    {
        const char* kp_src = (const char*)(g_kp + ((size_t)b * KK + kbase) * HH);
#pragma unroll
        for (int t = 0; t < 2; ++t) {
            const char* src = kp_src + (size_t)t * T2 * 256;
            unsigned char* dst = &s_kp[t][0];
#pragma unroll
            for (int i = 0; i < 2; ++i) {
                int c = tid + i * 256;               // 0..511 16B chunks
                int r = c >> 4, col = c & 15;
                cp_async16(dst + r * PITCHB + col * 16, src + c * 16);
            }
        }
        if (tid < 128) {   // 8 q rows x 256B = 128 x 16B chunks (byte arithmetic)
            int r = tid >> 4, c = tid & 15;
            cp_async16((char*)&s_q[r][0] + c * 16,
                       (const char*)(g_qp + (size_t)(b * QQ + q0 + r) * HH) + c * 16);
        }
        asm volatile("cp.async.commit_group;\n");
    }

    // v fragments from tiny precomputed f16 array (broadcast L1 hits)
    uint32_t vf[16];
    {
        const __half2* vh = (const __half2*)g_vh;
#pragma unroll
        for (int c = 0; c < 8; ++c) {
            vf[2 * c]     = h2u(vh[8 * c + t4]);
            vf[2 * c + 1] = h2u(vh[8 * c + t4 + 4]);
        }
    }

    const int bq = b * QQ + q0 + q;
    const int* mrow = mask + (size_t)bq * KK;
    float* aw = out_aw + (size_t)bq * KK;

    uint32_t sbase = (uint32_t)__cvta_generic_to_shared(&s_kp[0][0]);
    const int lrow = ((lane >> 3) & 1) * 8 + (lane & 7);
    const uint32_t laddr0 = sbase + (uint32_t)lrow * PITCHB + ((lane >> 4) ? 16u : 0u);

    asm volatile("cp.async.wait_group 0;\n");
    __syncthreads();   // the only barrier in this kernel

    // q fragments from smem (broadcast LDS)
    uint32_t qf[16];
    {
        const __half2* qrow = (const __half2*)&s_q[q][0];
#pragma unroll
        for (int c = 0; c < 8; ++c) {
            qf[2 * c]     = h2u(qrow[8 * c + t4]);
            qf[2 * c + 1] = h2u(qrow[8 * c + t4 + 4]);
        }
    }

#pragma unroll
    for (int t = 0; t < 2; ++t) {
#pragma unroll
        for (int half = 0; half < 2; ++half) {
            const uint32_t maddr = laddr0 + (uint32_t)t * TILEB
                                 + (uint32_t)half * 16u * PITCHB;
            float fA0 = 0.f, fA1 = 0.f, fA2 = 0.f, fA3 = 0.f;   // even chunks
            float fB0 = 0.f, fB1 = 0.f, fB2 = 0.f, fB3 = 0.f;   // odd chunks
#pragma unroll
            for (int c = 0; c < 8; c += 2) {
                uint32_t a0, a1, a2, a3, b0, b1, b2, b3;
                asm volatile("ldmatrix.sync.aligned.m8n8.x4.shared.b16 {%0,%1,%2,%3}, [%4];"
                             : "=r"(a0), "=r"(a1), "=r"(a2), "=r"(a3)
                             : "r"(maddr + 32u * c));
                asm volatile("ldmatrix.sync.aligned.m8n8.x4.shared.b16 {%0,%1,%2,%3}, [%4];"
                             : "=r"(b0), "=r"(b1), "=r"(b2), "=r"(b3)
                             : "r"(maddr + 32u * (c + 1)));
                a0 = htanh2(h2u(__hadd2(u2h(a0), u2h(qf[2 * c]))));
                a1 = htanh2(h2u(__hadd2(u2h(a1), u2h(qf[2 * c]))));
                a2 = htanh2(h2u(__hadd2(u2h(a2), u2h(qf[2 * c + 1]))));
                a3 = htanh2(h2u(__hadd2(u2h(a3), u2h(qf[2 * c + 1]))));
                b0 = htanh2(h2u(__hadd2(u2h(b0), u2h(qf[2 * c + 2]))));
                b1 = htanh2(h2u(__hadd2(u2h(b1), u2h(qf[2 * c + 2]))));
                b2 = htanh2(h2u(__hadd2(u2h(b2), u2h(qf[2 * c + 3]))));
                b3 = htanh2(h2u(__hadd2(u2h(b3), u2h(qf[2 * c + 3]))));
                asm volatile("mma.sync.aligned.m16n8k16.row.col.f32.f16.f16.f32 "
                             "{%0,%1,%2,%3}, {%4,%5,%6,%7}, {%8,%9}, {%0,%1,%2,%3};"
                             : "+f"(fA0), "+f"(fA1), "+f"(fA2), "+f"(fA3)
                             : "r"(a0), "r"(a1), "r"(a2), "r"(a3),
                               "r"(vf[2 * c]), "r"(vf[2 * c + 1]));
                asm volatile("mma.sync.aligned.m16n8k16.row.col.f32.f16.f16.f32 "
                             "{%0,%1,%2,%3}, {%4,%5,%6,%7}, {%8,%9}, {%0,%1,%2,%3};"
                             : "+f"(fB0), "+f"(fB1), "+f"(fB2), "+f"(fB3)
                             : "r"(b0), "r"(b1), "r"(b2), "r"(b3),
                               "r"(vf[2 * c + 2]), "r"(vf[2 * c + 3]));
            }
            if (t4 == 0) {
                int k0 = kbase + t * T2 + half * 16 + grp;
                int k1 = k0 + 8;
                // faithful to source: NEG_MASK_SCALE = -1e-09
                aw[k0] = (fA0 + fB0) + (-1e-9f) * (1.0f - (float)mrow[k0]);
                aw[k1] = (fA2 + fB2) + (-1e-9f) * (1.0f - (float)mrow[k1]);
            }
        }
    }
}

// ---------------- Softmax in-place on out_aw. Warp per row; grid 256 x 128 thr.
__global__ __launch_bounds__(128) void softmax_kernel(float* __restrict__ out_aw) {
    const int warp = threadIdx.x >> 5;
    const int lane = threadIdx.x & 31;
    const int bq = blockIdx.x * 4 + warp;

    float* aw = out_aw + (size_t)bq * KK;
    float vals[32];
    float mx = -1e30f;
#pragma unroll
    for (int j = 0; j < 32; ++j) {
        float s = aw[lane + j * 32];
        vals[j] = s;
        mx = fmaxf(mx, s);
    }
#pragma unroll
    for (int o = 16; o; o >>= 1) mx = fmaxf(mx, __shfl_xor_sync(~0u, mx, o));
    float sum = 0.f;
#pragma unroll
    for (int j = 0; j < 32; ++j) { float e = __expf(vals[j] - mx); vals[j] = e; sum += e; }
#pragma unroll
    for (int o = 16; o; o >>= 1) sum += __shfl_xor_sync(~0u, sum, o);
    float inv = 1.0f / sum;
#pragma unroll
    for (int j = 0; j < 32; ++j) aw[lane + j * 32] = vals[j] * inv;
}

// ---------------- Context partial GEMM: 32q x 128h x 64k per block, smem-staged value.
__global__ __launch_bounds__(256) void ctx_kernel(const float* __restrict__ value,
                                                  const float* __restrict__ out_aw) {
    __shared__ float s_w[CQT * CKCH];        // 8 KB
    __shared__ __align__(16) float s_v[2][CT * HH];  // 32 KB

    const int tid = threadIdx.x;
    const int bx = blockIdx.x;
    const int b = bx >> 7;
    const int qt = (bx >> 4) & 7;
    const int ks = bx & 15;
    const int q0 = qt * CQT;
    const int kbase = ks * CKCH;

    const float* vsrc = value + ((size_t)b * KK + kbase) * HH;

    auto stage = [&](int t, int buf) {
        const float4* src = (const float4*)(vsrc + (size_t)t * CT * HH);
        float4* dst = (float4*)&s_v[buf][0];
#pragma unroll
        for (int i = 0; i < 4; ++i) {
            int idx = tid + i * 256;   // 0..1023
            cp_async16(dst + idx, src + idx);
        }
        asm volatile("cp.async.commit_group;\n");
    };

    stage(0, 0);

    {
        int idx = tid;
#pragma unroll
        for (int i = 0; i < 2; ++i, idx += 256) {
            int r = idx >> 4, c = idx & 15;
            ((float4*)s_w)[idx] =
                ((const float4*)(out_aw + (size_t)(b * QQ + q0 + r) * KK + kbase))[c];
        }
    }

    const int h4 = tid & 31;
    const int qs = tid >> 5;
    const float* w0 = s_w + (qs * 4 + 0) * CKCH;
    const float* w1 = s_w + (qs * 4 + 1) * CKCH;
    const float* w2 = s_w + (qs * 4 + 2) * CKCH;
    const float* w3 = s_w + (qs * 4 + 3) * CKCH;

    float4 A0 = {0,0,0,0}, A1 = {0,0,0,0}, A2 = {0,0,0,0}, A3 = {0,0,0,0};

    for (int t = 0; t < CKCH / CT; ++t) {
        const int buf = t & 1;
        if (t < CKCH / CT - 1) {
            stage(t + 1, buf ^ 1);
            asm volatile("cp.async.wait_group 1;\n");
        } else {
            asm volatile("cp.async.wait_group 0;\n");
        }
        __syncthreads();

        const float4* vt = (const float4*)&s_v[buf][0] + h4;
        const int kb = t * CT;
#pragma unroll 4
        for (int k = 0; k < CT; ++k) {
            float4 v = vt[k * 32];
            float a = w0[kb + k], c = w1[kb + k], d = w2[kb + k], e = w3[kb + k];
            A0.x += a * v.x; A0.y += a * v.y; A0.z += a * v.z; A0.w += a * v.w;
            A1.x += c * v.x; A1.y += c * v.y; A1.z += c * v.z; A1.w += c * v.w;
            A2.x += d * v.x; A2.y += d * v.y; A2.z += d * v.z; A2.w += d * v.w;
            A3.x += e * v.x; A3.y += e * v.y; A3.z += e * v.z; A3.w += e * v.w;
        }
        __syncthreads();
    }

    float* dst = g_cpart + (size_t)ks * (BB * QQ * HH)
               + (size_t)(b * QQ + q0 + qs * 4) * HH;
    ((float4*)dst)[h4] = A0;
    ((float4*)(dst + HH))[h4] = A1;
    ((float4*)(dst + 2 * HH))[h4] = A2;
    ((float4*)(dst + 3 * HH))[h4] = A3;
}

// ---------------- Reduce ctx partials (16-way). grid 512 x 256.
__global__ __launch_bounds__(256) void ctx_reduce_kernel(float* __restrict__ out_ctx) {
    int i = blockIdx.x * 256 + threadIdx.x;   // 0 .. 131071
    const int N = BB * QQ * HH;
    float s = 0.f;
#pragma unroll
    for (int p = 0; p < CKS; ++p) s += g_cpart[p * N + i];
    out_ctx[i] = s;
}

extern "C" void kernel_launch(void* const* d_in, const int* in_sizes, int n_in,
                              void* d_out, int out_size) {
    // metadata order: query, key, value, mask, Wq, Wk, v
    const float* query = (const float*)d_in[0];
    const float* key   = (const float*)d_in[1];
    const float* value = (const float*)d_in[2];
    const int*   mask  = (const int*)d_in[3];
    const float* Wq    = (const float*)d_in[4];
    const float* Wk    = (const float*)d_in[5];
    const float* vvec  = (const float*)d_in[6];

    float* out_aw  = (float*)d_out;                          // (B,Q,K)
    float* out_ctx = out_aw + (size_t)BB * QQ * KK;          // (B,Q,H)

    const int proj_smem = (32 * 128 + 64 * 132) * (int)sizeof(float);  // 50688 B
    cudaFuncSetAttribute(proj_kernel, cudaFuncAttributeMaxDynamicSharedMemorySize, proj_smem);

    proj_kernel<<<320, 256, proj_smem>>>(query, key, Wq, Wk, vvec);
    score_kernel<<<BB * (QQ / QT) * KS, 256>>>(mask, out_aw);
    softmax_kernel<<<BB * QQ / 4, 128>>>(out_aw);
    ctx_kernel<<<BB * (QQ / CQT) * CKS, 256>>>(value, out_aw);
    ctx_reduce_kernel<<<BB * QQ * HH / 256, 256>>>(out_ctx);
}

// round 16
// speedup vs baseline: 1.0385x; 1.0385x over previous
#include <cuda_runtime.h>
#include <cuda_bf16.h>
#include <cuda_fp16.h>
#include <cstdint>
#include <cstring>

// Problem constants (B=4, Q=256, K=1024, H=128)
#define BB 4
#define QQ 256
#define HH 128
#define KK 1024
#define QT 8             // queries per score block (one per warp)
#define KS 16            // k-splits per query row (score)
#define KCH (KK / KS)    // 64 k-rows per score block (= 2 tiles)
#define T2 32            // k-rows per stage tile
#define PITCHB 272       // bytes per smem tile row (256 data + 16 pad)
#define TILEB (T2 * PITCHB)  // 8704 bytes per buffer
#define CKS 16           // ctx k-splits
#define CKCH (KK / CKS)  // 64 k per ctx block
#define CQT 32           // ctx queries per block
#define CT 32            // ctx k-rows per stage tile

// Scratch (device globals — no allocation allowed)
__device__ __half g_qp[BB * QQ * HH];          // 256 KB
__device__ __half g_kp[BB * KK * HH];          // 1 MB
__device__ __half g_vh[HH];                    // f16 copy of v
__device__ float  g_ssum[BB * QQ * KS];        // 64 KB exp partial sums
__device__ float  g_cpart[CKS * BB * QQ * HH]; // 8 MB ctx partials

__device__ __forceinline__ uint32_t h2u(__half2 h) { uint32_t u; memcpy(&u, &h, 4); return u; }
__device__ __forceinline__ __half2 u2h(uint32_t u) { __half2 h; memcpy(&h, &u, 4); return h; }

__device__ __forceinline__ uint32_t htanh2(uint32_t a) {
    uint32_t r;
    asm("tanh.approx.f16x2 %0, %1;" : "=r"(r) : "r"(a));
    return r;
}

__device__ __forceinline__ void cp_async16(void* dst, const void* src) {
    uint32_t d = (uint32_t)__cvta_generic_to_shared(dst);
    asm volatile("cp.async.ca.shared.global [%0], [%1], 16;\n" :: "r"(d), "l"(src));
}

// ---------------- Projection GEMM: out[row][h] = sum_d in[row][d] * W[h][d]
// Block 0 also publishes the f16 copy of v (g_vh).
__global__ __launch_bounds__(256, 2) void proj_kernel(
    const float* __restrict__ query, const float* __restrict__ key,
    const float* __restrict__ Wq, const float* __restrict__ Wk,
    const float* __restrict__ vvec) {
    extern __shared__ float psm[];
    float4* s_a = (float4*)psm;                   // [32][32] float4, pitch 32
    float4* s_b = (float4*)(psm + 32 * 128);      // [64][33] float4, pitch 33

    if (blockIdx.x == 0 && threadIdx.x < HH)
        g_vh[threadIdx.x] = __float2half(vvec[threadIdx.x]);

    int bx = blockIdx.x;
    const float* in; const float* W; __half* out;
    int rowTile, hTile;
    if (bx < 64) { in = query; W = Wq; out = g_qp; rowTile = (bx >> 1) * 32; hTile = (bx & 1) * 64; }
    else { bx -= 64; in = key; W = Wk; out = g_kp; rowTile = (bx >> 1) * 32; hTile = (bx & 1) * 64; }

    const int tid = threadIdx.x;
    const int tx = tid & 15;
    const int ty = tid >> 4;

    {
        const float4* in4 = (const float4*)(in + (size_t)rowTile * HH);
        const float4* w4 = (const float4*)(W + (size_t)hTile * HH);
        int idx = tid;
#pragma unroll
        for (int i = 0; i < 4; ++i, idx += 256) {
            int r = idx >> 5, c = idx & 31;
            s_a[r * 32 + c] = in4[r * 32 + c];
        }
        idx = tid;
#pragma unroll
        for (int i = 0; i < 8; ++i, idx += 256) {
            int r = idx >> 5, c = idx & 31;
            s_b[r * 33 + c] = w4[r * 32 + c];
        }
    }
    __syncthreads();

    float acc[2][4] = {};
#pragma unroll
    for (int s = 0; s < 32; ++s) {
        float4 a[2], b[4];
#pragma unroll
        for (int i = 0; i < 2; ++i) a[i] = s_a[(ty + 16 * i) * 32 + s];
#pragma unroll
        for (int j = 0; j < 4; ++j) b[j] = s_b[(tx + 16 * j) * 33 + s];
#pragma unroll
        for (int i = 0; i < 2; ++i)
#pragma unroll
            for (int j = 0; j < 4; ++j)
                acc[i][j] += a[i].x * b[j].x + a[i].y * b[j].y
                           + a[i].z * b[j].z + a[i].w * b[j].w;
    }

#pragma unroll
    for (int i = 0; i < 2; ++i)
#pragma unroll
        for (int j = 0; j < 4; ++j)
            out[(size_t)(rowTile + ty + 16 * i) * HH + hTile + tx + 16 * j] =
                __float2half(acc[i][j]);
}

// ---------------- Score kernel: HMMA over tanh(qp+kp) features.
// Writes UNNORMALIZED exp(masked score) to aw, plus per-(row, ks) exp partial
// sums to g_ssum (softmax fused; scores bounded ~|9| so no max-shift needed).
__global__ __launch_bounds__(256, 4) void score_kernel(const int* __restrict__ mask,
                                                       float* __restrict__ out_aw) {
    __shared__ __align__(16) unsigned char s_kp[2][TILEB];
    __shared__ __align__(16) __half s_q[QT][HH];   // 2 KB

    const int tid = threadIdx.x;
    const int bx = blockIdx.x;
    const int b = bx >> 9;
    const int qt = (bx >> 4) & 31;
    const int ks = bx & 15;
    const int q0 = qt * QT;
    const int kbase = ks * KCH;
    const int lane = tid & 31;
    const int q = tid >> 5;           // warp == query
    const int t4 = lane & 3;
    const int grp = lane >> 2;

    // ---- stage BOTH kp tiles + 8 q rows up-front (single commit)
    {
        const char* kp_src = (const char*)(g_kp + ((size_t)b * KK + kbase) * HH);
#pragma unroll
        for (int t = 0; t < 2; ++t) {
            const char* src = kp_src + (size_t)t * T2 * 256;
            unsigned char* dst = &s_kp[t][0];
#pragma unroll
            for (int i = 0; i < 2; ++i) {
                int c = tid + i * 256;               // 0..511 16B chunks
                int r = c >> 4, col = c & 15;
                cp_async16(dst + r * PITCHB + col * 16, src + c * 16);
            }
        }
        if (tid < 128) {   // 8 q rows x 256B = 128 x 16B chunks (byte arithmetic)
            int r = tid >> 4, c = tid & 15;
            cp_async16((char*)&s_q[r][0] + c * 16,
                       (const char*)(g_qp + (size_t)(b * QQ + q0 + r) * HH) + c * 16);
        }
        asm volatile("cp.async.commit_group;\n");
    }

    // v fragments from tiny precomputed f16 array (broadcast L1 hits)
    uint32_t vf[16];
    {
        const __half2* vh = (const __half2*)g_vh;
#pragma unroll
        for (int c = 0; c < 8; ++c) {
            vf[2 * c]     = h2u(vh[8 * c + t4]);
            vf[2 * c + 1] = h2u(vh[8 * c + t4 + 4]);
        }
    }

    const int bq = b * QQ + q0 + q;
    const int* mrow = mask + (size_t)bq * KK;
    float* aw = out_aw + (size_t)bq * KK;

    uint32_t sbase = (uint32_t)__cvta_generic_to_shared(&s_kp[0][0]);
    const int lrow = ((lane >> 3) & 1) * 8 + (lane & 7);
    const uint32_t laddr0 = sbase + (uint32_t)lrow * PITCHB + ((lane >> 4) ? 16u : 0u);

    asm volatile("cp.async.wait_group 0;\n");
    __syncthreads();   // the only barrier in this kernel

    // q fragments from smem (broadcast LDS)
    uint32_t qf[16];
    {
        const __half2* qrow = (const __half2*)&s_q[q][0];
#pragma unroll
        for (int c = 0; c < 8; ++c) {
            qf[2 * c]     = h2u(qrow[8 * c + t4]);
            qf[2 * c + 1] = h2u(qrow[8 * c + t4 + 4]);
        }
    }

    float wsum = 0.f;    // per-lane partial of exp sum (nonzero only on t4==0)

#pragma unroll
    for (int t = 0; t < 2; ++t) {
#pragma unroll
        for (int half = 0; half < 2; ++half) {
            const uint32_t maddr = laddr0 + (uint32_t)t * TILEB
                                 + (uint32_t)half * 16u * PITCHB;
            float fA0 = 0.f, fA1 = 0.f, fA2 = 0.f, fA3 = 0.f;   // even chunks
            float fB0 = 0.f, fB1 = 0.f, fB2 = 0.f, fB3 = 0.f;   // odd chunks
#pragma unroll
            for (int c = 0; c < 8; c += 2) {
                uint32_t a0, a1, a2, a3, b0, b1, b2, b3;
                asm volatile("ldmatrix.sync.aligned.m8n8.x4.shared.b16 {%0,%1,%2,%3}, [%4];"
                             : "=r"(a0), "=r"(a1), "=r"(a2), "=r"(a3)
                             : "r"(maddr + 32u * c));
                asm volatile("ldmatrix.sync.aligned.m8n8.x4.shared.b16 {%0,%1,%2,%3}, [%4];"
                             : "=r"(b0), "=r"(b1), "=r"(b2), "=r"(b3)
                             : "r"(maddr + 32u * (c + 1)));
                a0 = htanh2(h2u(__hadd2(u2h(a0), u2h(qf[2 * c]))));
                a1 = htanh2(h2u(__hadd2(u2h(a1), u2h(qf[2 * c]))));
                a2 = htanh2(h2u(__hadd2(u2h(a2), u2h(qf[2 * c + 1]))));
                a3 = htanh2(h2u(__hadd2(u2h(a3), u2h(qf[2 * c + 1]))));
                b0 = htanh2(h2u(__hadd2(u2h(b0), u2h(qf[2 * c + 2]))));
                b1 = htanh2(h2u(__hadd2(u2h(b1), u2h(qf[2 * c + 2]))));
                b2 = htanh2(h2u(__hadd2(u2h(b2), u2h(qf[2 * c + 3]))));
                b3 = htanh2(h2u(__hadd2(u2h(b3), u2h(qf[2 * c + 3]))));
                asm volatile("mma.sync.aligned.m16n8k16.row.col.f32.f16.f16.f32 "
                             "{%0,%1,%2,%3}, {%4,%5,%6,%7}, {%8,%9}, {%0,%1,%2,%3};"
                             : "+f"(fA0), "+f"(fA1), "+f"(fA2), "+f"(fA3)
                             : "r"(a0), "r"(a1), "r"(a2), "r"(a3),
                               "r"(vf[2 * c]), "r"(vf[2 * c + 1]));
                asm volatile("mma.sync.aligned.m16n8k16.row.col.f32.f16.f16.f32 "
                             "{%0,%1,%2,%3}, {%4,%5,%6,%7}, {%8,%9}, {%0,%1,%2,%3};"
                             : "+f"(fB0), "+f"(fB1), "+f"(fB2), "+f"(fB3)
                             : "r"(b0), "r"(b1), "r"(b2), "r"(b3),
                               "r"(vf[2 * c + 2]), "r"(vf[2 * c + 3]));
            }
            if (t4 == 0) {
                int k0 = kbase + t * T2 + half * 16 + grp;
                int k1 = k0 + 8;
                // faithful to source: NEG_MASK_SCALE = -1e-09
                float s0 = (fA0 + fB0) + (-1e-9f) * (1.0f - (float)mrow[k0]);
                float s1 = (fA2 + fB2) + (-1e-9f) * (1.0f - (float)mrow[k1]);
                float e0 = __expf(s0);     // scores bounded (~|9|): no max-shift
                float e1 = __expf(s1);
                aw[k0] = e0;
                aw[k1] = e1;
                wsum += e0 + e1;
            }
        }
    }

    // deterministic warp reduction of this warp's exp partial sum
#pragma unroll
    for (int o = 16; o; o >>= 1) wsum += __shfl_xor_sync(~0u, wsum, o);
    if (lane == 0) g_ssum[(size_t)bq * KS + ks] = wsum;
}

// ---------------- Context partial GEMM + softmax finalize.
// 32q x 128h x 64k per block. Reconstructs row inv-sums from g_ssum, rescales
// the staged weight chunk, writes final normalized aw, then partial ctx GEMM.
__global__ __launch_bounds__(256) void ctx_kernel(const float* __restrict__ value,
                                                  float* __restrict__ out_aw) {
    __shared__ float s_w[CQT * CKCH];        // 8 KB
    __shared__ float s_inv[CQT];
    __shared__ __align__(16) float s_v[2][CT * HH];  // 32 KB

    const int tid = threadIdx.x;
    const int bx = blockIdx.x;
    const int b = bx >> 7;
    const int qt = (bx >> 4) & 7;
    const int ks = bx & 15;
    const int q0 = qt * CQT;
    const int kbase = ks * CKCH;

    const float* vsrc = value + ((size_t)b * KK + kbase) * HH;

    auto stage = [&](int t, int buf) {
        const float4* src = (const float4*)(vsrc + (size_t)t * CT * HH);
        float4* dst = (float4*)&s_v[buf][0];
#pragma unroll
        for (int i = 0; i < 4; ++i) {
            int idx = tid + i * 256;   // 0..1023
            cp_async16(dst + idx, src + idx);
        }
        asm volatile("cp.async.commit_group;\n");
    };

    stage(0, 0);

    // stage weights (unnormalized exp): 32 rows x 16 float4, 2/thread
    {
        int idx = tid;
#pragma unroll
        for (int i = 0; i < 2; ++i, idx += 256) {
            int r = idx >> 4, c = idx & 15;
            ((float4*)s_w)[idx] =
                ((const float4*)(out_aw + (size_t)(b * QQ + q0 + r) * KK + kbase))[c];
        }
    }

    // row inverse sums from the 16 score-block partials (deterministic order)
    if (tid < CQT) {
        const float* ps = g_ssum + (size_t)(b * QQ + q0 + tid) * KS;
        float s = 0.f;
#pragma unroll
        for (int j = 0; j < KS; ++j) s += ps[j];
        s_inv[tid] = 1.0f / s;
    }
    __syncthreads();

    // normalize staged weights in smem + write final aw chunk
    {
        int idx = tid;
#pragma unroll
        for (int i = 0; i < 2; ++i, idx += 256) {
            int r = idx >> 4, c = idx & 15;
            float inv = s_inv[r];
            float4 w = ((float4*)s_w)[idx];
            w.x *= inv; w.y *= inv; w.z *= inv; w.w *= inv;
            ((float4*)s_w)[idx] = w;
            ((float4*)(out_aw + (size_t)(b * QQ + q0 + r) * KK + kbase))[c] = w;
        }
    }

    const int h4 = tid & 31;
    const int qs = tid >> 5;
    const float* w0 = s_w + (qs * 4 + 0) * CKCH;
    const float* w1 = s_w + (qs * 4 + 1) * CKCH;
    const float* w2 = s_w + (qs * 4 + 2) * CKCH;
    const float* w3 = s_w + (qs * 4 + 3) * CKCH;

    float4 A0 = {0,0,0,0}, A1 = {0,0,0,0}, A2 = {0,0,0,0}, A3 = {0,0,0,0};

    for (int t = 0; t < CKCH / CT; ++t) {
        const int buf = t & 1;
        if (t < CKCH / CT - 1) {
            stage(t + 1, buf ^ 1);
            asm volatile("cp.async.wait_group 1;\n");
        } else {
            asm volatile("cp.async.wait_group 0;\n");
        }
        __syncthreads();

        const float4* vt = (const float4*)&s_v[buf][0] + h4;
        const int kb = t * CT;
#pragma unroll 4
        for (int k = 0; k < CT; ++k) {
            float4 v = vt[k * 32];
            float a = w0[kb + k], c = w1[kb + k], d = w2[kb + k], e = w3[kb + k];
            A0.x += a * v.x; A0.y += a * v.y; A0.z += a * v.z; A0.w += a * v.w;
            A1.x += c * v.x; A1.y += c * v.y; A1.z += c * v.z; A1.w += c * v.w;
            A2.x += d * v.x; A2.y += d * v.y; A2.z += d * v.z; A2.w += d * v.w;
            A3.x += e * v.x; A3.y += e * v.y; A3.z += e * v.z; A3.w += e * v.w;
        }
        __syncthreads();
    }

    float* dst = g_cpart + (size_t)ks * (BB * QQ * HH)
               + (size_t)(b * QQ + q0 + qs * 4) * HH;
    ((float4*)dst)[h4] = A0;
    ((float4*)(dst + HH))[h4] = A1;
    ((float4*)(dst + 2 * HH))[h4] = A2;
    ((float4*)(dst + 3 * HH))[h4] = A3;
}

// ---------------- Reduce ctx partials (16-way). grid 512 x 256.
__global__ __launch_bounds__(256) void ctx_reduce_kernel(float* __restrict__ out_ctx) {
    int i = blockIdx.x * 256 + threadIdx.x;   // 0 .. 131071
    const int N = BB * QQ * HH;
    float s = 0.f;
#pragma unroll
    for (int p = 0; p < CKS; ++p) s += g_cpart[p * N + i];
    out_ctx[i] = s;
}

extern "C" void kernel_launch(void* const* d_in, const int* in_sizes, int n_in,
                              void* d_out, int out_size) {
    // metadata order: query, key, value, mask, Wq, Wk, v
    const float* query = (const float*)d_in[0];
    const float* key   = (const float*)d_in[1];
    const float* value = (const float*)d_in[2];
    const int*   mask  = (const int*)d_in[3];
    const float* Wq    = (const float*)d_in[4];
    const float* Wk    = (const float*)d_in[5];
    const float* vvec  = (const float*)d_in[6];

    float* out_aw  = (float*)d_out;                          // (B,Q,K)
    float* out_ctx = out_aw + (size_t)BB * QQ * KK;          // (B,Q,H)

    const int proj_smem = (32 * 128 + 64 * 132) * (int)sizeof(float);  // 50688 B
    cudaFuncSetAttribute(proj_kernel, cudaFuncAttributeMaxDynamicSharedMemorySize, proj_smem);

    proj_kernel<<<320, 256, proj_smem>>>(query, key, Wq, Wk, vvec);
    score_kernel<<<BB * (QQ / QT) * KS, 256>>>(mask, out_aw);
    ctx_kernel<<<BB * (QQ / CQT) * CKS, 256>>>(value, out_aw);
    ctx_reduce_kernel<<<BB * QQ * HH / 256, 256>>>(out_ctx);
}